// round 14
// baseline (speedup 1.0000x reference)
#include <cuda_runtime.h>
#include <cuda_bf16.h>
#include <cstdint>

#define B_ROWS 4096
#define D_IN   1024
#define HID    32768
#define TOPK   32
#define NCAND  48
#define CAP    96

// ---------------- static device scratch ----------------
__device__ __nv_bfloat16 g_Wb[(size_t)HID * D_IN];
__device__ __nv_bfloat16 g_xb[(size_t)B_ROWS * D_IN];
__device__ __align__(16) __nv_bfloat16 g_pre[(size_t)B_ROWS * HID];
__device__ int   g_cand[B_ROWS * CAP];
__device__ int   g_ncand[B_ROWS];
__device__ float g_topv[B_ROWS * TOPK];
__device__ int   g_topi[B_ROWS * TOPK];

__device__ __forceinline__ uint32_t pack_bf16x2(float lo, float hi) {
    uint32_t r;
    asm("cvt.rn.bf16x2.f32 %0, %1, %2;" : "=r"(r) : "f"(hi), "f"(lo));
    return r;
}

// ---------------- converters ----------------
__global__ void k_convW(const float* __restrict__ W) {
    size_t n = (size_t)HID * D_IN / 8;
    const float4* src = reinterpret_cast<const float4*>(W);
    uint4* dst = reinterpret_cast<uint4*>(g_Wb);
    for (size_t i = (size_t)blockIdx.x * blockDim.x + threadIdx.x; i < n;
         i += (size_t)gridDim.x * blockDim.x) {
        float4 a = src[2 * i], b = src[2 * i + 1];
        uint4 o;
        o.x = pack_bf16x2(a.x, a.y);
        o.y = pack_bf16x2(a.z, a.w);
        o.z = pack_bf16x2(b.x, b.y);
        o.w = pack_bf16x2(b.z, b.w);
        dst[i] = o;
    }
}

__global__ void k_convX(const float* __restrict__ x, const float* __restrict__ b_dec) {
    size_t n = (size_t)B_ROWS * D_IN;
    for (size_t i = (size_t)blockIdx.x * blockDim.x + threadIdx.x; i < n;
         i += (size_t)gridDim.x * blockDim.x) {
        int d = (int)(i & (D_IN - 1));
        g_xb[i] = __float2bfloat16(x[i] - b_dec[d]);
    }
}

// ---------- GEMM: 128x256 tile, BK=32, 3-stage cp.async (72KB dyn smem) ----
#define BM 128
#define BN 256
#define BK 32
#define KT (D_IN / BK)
#define STG 24576            // A 8KB + B 16KB
#define GEMM_SMEM (3 * STG)  // 72 KB

__device__ __forceinline__ uint32_t swz32(uint32_t r, uint32_t c) {
    uint32_t pr = r >> 1;
    uint32_t pc = (c + ((r & 1u) << 2)) ^ (pr & 7u);
    return pr * 128u + (pc << 4);
}

__global__ __launch_bounds__(256, 1) void k_gemm(const float* __restrict__ b_enc) {
    extern __shared__ __align__(16) uint8_t smem[];

    const int tid  = threadIdx.x;
    const int wid  = tid >> 5;
    const int lane = tid & 31;
    const int bm0  = blockIdx.y * BM;
    const int bn0  = blockIdx.x * BN;
    const int warp_m = (wid >> 2) * 64;   // 2 warps along M
    const int warp_n = (wid & 3) * 64;    // 4 warps along N

    float acc[4][8][4];
    #pragma unroll
    for (int a = 0; a < 4; a++)
        #pragma unroll
        for (int b = 0; b < 8; b++)
            #pragma unroll
            for (int c = 0; c < 4; c++) acc[a][b][c] = 0.f;

    auto issueLoads = [&](int kt, int stage) {
        const __nv_bfloat16* Asrc = g_xb + (size_t)bm0 * D_IN + kt * BK;
        const __nv_bfloat16* Bsrc = g_Wb + (size_t)bn0 * D_IN + kt * BK;
        uint8_t* As = smem + stage * STG;
        uint8_t* Bs = As + 8192;
        #pragma unroll
        for (int i = 0; i < 2; i++) {        // A: 128 rows x 4 chunks
            int id = tid + 256 * i;
            int r = id >> 2, c = id & 3;
            uint32_t da = (uint32_t)__cvta_generic_to_shared(As + swz32(r, c));
            const void* sa = Asrc + (size_t)r * D_IN + c * 8;
            asm volatile("cp.async.cg.shared.global [%0], [%1], 16;\n" :: "r"(da), "l"(sa));
        }
        #pragma unroll
        for (int i = 0; i < 4; i++) {        // B: 256 rows x 4 chunks
            int id = tid + 256 * i;
            int r = id >> 2, c = id & 3;
            uint32_t db = (uint32_t)__cvta_generic_to_shared(Bs + swz32(r, c));
            const void* sb = Bsrc + (size_t)r * D_IN + c * 8;
            asm volatile("cp.async.cg.shared.global [%0], [%1], 16;\n" :: "r"(db), "l"(sb));
        }
    };

    auto computeStage = [&](int stage) {
        uint8_t* As = smem + stage * STG;
        uint8_t* Bs = As + 8192;
        #pragma unroll
        for (int ks = 0; ks < 2; ks++) {
            uint32_t a[4][4], b[4][4];
            #pragma unroll
            for (int im = 0; im < 4; im++) {
                int r = warp_m + im * 16 + (lane & 15);
                int c = ks * 2 + (lane >> 4);
                uint32_t addr = (uint32_t)__cvta_generic_to_shared(As + swz32(r, c));
                asm volatile("ldmatrix.sync.aligned.m8n8.x4.shared.b16 {%0,%1,%2,%3}, [%4];\n"
                             : "=r"(a[im][0]), "=r"(a[im][1]), "=r"(a[im][2]), "=r"(a[im][3])
                             : "r"(addr));
            }
            #pragma unroll
            for (int in2 = 0; in2 < 4; in2++) {
                int r = warp_n + in2 * 16 + (lane & 7) + ((lane & 16) ? 8 : 0);
                int c = ks * 2 + ((lane >> 3) & 1);
                uint32_t addr = (uint32_t)__cvta_generic_to_shared(Bs + swz32(r, c));
                asm volatile("ldmatrix.sync.aligned.m8n8.x4.shared.b16 {%0,%1,%2,%3}, [%4];\n"
                             : "=r"(b[in2][0]), "=r"(b[in2][1]), "=r"(b[in2][2]), "=r"(b[in2][3])
                             : "r"(addr));
            }
            #pragma unroll
            for (int im = 0; im < 4; im++)
                #pragma unroll
                for (int in8 = 0; in8 < 8; in8++) {
                    uint32_t b0 = b[in8 >> 1][(in8 & 1) * 2 + 0];
                    uint32_t b1 = b[in8 >> 1][(in8 & 1) * 2 + 1];
                    float* c4 = acc[im][in8];
                    asm volatile(
                        "mma.sync.aligned.m16n8k16.row.col.f32.bf16.bf16.f32 "
                        "{%0,%1,%2,%3},{%4,%5,%6,%7},{%8,%9},{%0,%1,%2,%3};\n"
                        : "+f"(c4[0]), "+f"(c4[1]), "+f"(c4[2]), "+f"(c4[3])
                        : "r"(a[im][0]), "r"(a[im][1]), "r"(a[im][2]), "r"(a[im][3]),
                          "r"(b0), "r"(b1));
                }
        }
    };

    issueLoads(0, 0);
    asm volatile("cp.async.commit_group;\n" ::: "memory");
    issueLoads(1, 1);
    asm volatile("cp.async.commit_group;\n" ::: "memory");

    for (int kt = 0; kt < KT; kt++) {
        asm volatile("cp.async.wait_group 1;\n" ::: "memory");
        __syncthreads();
        if (kt + 2 < KT) issueLoads(kt + 2, (kt + 2) % 3);
        asm volatile("cp.async.commit_group;\n" ::: "memory");
        computeStage(kt % 3);
    }

    const int r0 = bm0 + warp_m + (lane >> 2);
    const int c0 = bn0 + warp_n + (lane & 3) * 2;
    #pragma unroll
    for (int im = 0; im < 4; im++)
        #pragma unroll
        for (int in8 = 0; in8 < 8; in8++) {
            int r = r0 + im * 16;
            int h = c0 + in8 * 8;
            float be0 = b_enc[h], be1 = b_enc[h + 1];
            float v0 = fmaxf(acc[im][in8][0] + be0, 0.f);
            float v1 = fmaxf(acc[im][in8][1] + be1, 0.f);
            float v2 = fmaxf(acc[im][in8][2] + be0, 0.f);
            float v3 = fmaxf(acc[im][in8][3] + be1, 0.f);
            *reinterpret_cast<uint32_t*>(&g_pre[(size_t)r * HID + h]) = pack_bf16x2(v0, v1);
            *reinterpret_cast<uint32_t*>(&g_pre[(size_t)(r + 8) * HID + h]) = pack_bf16x2(v2, v3);
        }
}

// ------- top-NCAND selection: 12-bit hist + exact 16-bit refinement --------
// (round-11 version, measured 148 us)
__global__ __launch_bounds__(256) void k_select() {
    const int row = blockIdx.x;
    const int tid = threadIdx.x, lane = tid & 31, wi = tid >> 5;
    const uint4* kp4 = reinterpret_cast<const uint4*>(g_pre + (size_t)row * HID);
    __shared__ int hist[4096];
    __shared__ int sub[16];
    __shared__ int warpsum[8];
    __shared__ int sB1, sAbove, sThr, sCnt;

    #pragma unroll
    for (int i = 0; i < 16; i++) hist[tid + 256 * i] = 0;
    if (tid < 16) sub[tid] = 0;
    if (tid == 0) { sB1 = -1; sAbove = 0; sThr = 1; sCnt = 0; }
    __syncthreads();

    for (int i = tid; i < HID / 8; i += 256) {
        uint4 u = kp4[i];
        uint32_t ws[4] = {u.x, u.y, u.z, u.w};
        #pragma unroll
        for (int q = 0; q < 4; q++) {
            uint32_t k0 = ws[q] & 0xFFFFu, k1 = ws[q] >> 16;
            if (k0) atomicAdd(&hist[k0 >> 4], 1);
            if (k1) atomicAdd(&hist[k1 >> 4], 1);
        }
    }
    __syncthreads();

    const int base = 4095 - tid * 16;
    int s = 0;
    #pragma unroll
    for (int j = 0; j < 16; j++) s += hist[base - j];
    int inc = s;
    #pragma unroll
    for (int o = 1; o < 32; o <<= 1) {
        int v = __shfl_up_sync(0xffffffffu, inc, o);
        if (lane >= o) inc += v;
    }
    if (lane == 31) warpsum[wi] = inc;
    __syncthreads();
    if (wi == 0) {
        int wsv = (lane < 8) ? warpsum[lane] : 0;
        #pragma unroll
        for (int o = 1; o < 8; o <<= 1) {
            int v = __shfl_up_sync(0xffffffffu, wsv, o);
            if (lane >= o) wsv += v;
        }
        if (lane < 8) warpsum[lane] = wsv;
    }
    __syncthreads();
    const int above0 = inc - s + (wi ? warpsum[wi - 1] : 0);
    if (above0 < NCAND && above0 + s >= NCAND) {
        int cum = above0;
        #pragma unroll
        for (int j = 0; j < 16; j++) {
            int b = base - j;
            int hb = hist[b];
            if (cum + hb >= NCAND) { sB1 = b; sAbove = cum; break; }
            cum += hb;
        }
    }
    __syncthreads();
    const int B1 = sB1;

    if (B1 >= 0) {
        for (int i = tid; i < HID / 8; i += 256) {
            uint4 u = kp4[i];
            uint32_t ws[4] = {u.x, u.y, u.z, u.w};
            #pragma unroll
            for (int q = 0; q < 4; q++) {
                uint32_t k0 = ws[q] & 0xFFFFu, k1 = ws[q] >> 16;
                if ((int)(k0 >> 4) == B1) atomicAdd(&sub[k0 & 15u], 1);
                if ((int)(k1 >> 4) == B1) atomicAdd(&sub[k1 & 15u], 1);
            }
        }
    }
    __syncthreads();
    if (tid == 0 && B1 >= 0) {
        int cum = sAbove;
        for (int c2 = 15; c2 >= 0; c2--) {
            cum += sub[c2];
            if (cum >= NCAND) { sThr = (B1 << 4) | c2; break; }
        }
    }
    __syncthreads();
    const uint32_t thr = (uint32_t)sThr;

    for (int i = tid; i < HID / 8; i += 256) {
        uint4 u = kp4[i];
        uint32_t ws[4] = {u.x, u.y, u.z, u.w};
        #pragma unroll
        for (int q = 0; q < 4; q++) {
            #pragma unroll
            for (int h = 0; h < 2; h++) {
                uint32_t k = h ? (ws[q] >> 16) : (ws[q] & 0xFFFFu);
                if (k >= thr) {
                    int p = atomicAdd(&sCnt, 1);
                    if (p < CAP) g_cand[row * CAP + p] = i * 8 + q * 2 + h;
                }
            }
        }
    }
    __syncthreads();
    if (tid == 0) g_ncand[row] = min(sCnt, CAP);
}

// ---------------- exact recompute (fp32 compensated) + top-32 ---------------
__global__ __launch_bounds__(256) void k_exact(const float* __restrict__ x,
                                               const float* __restrict__ b_dec,
                                               const float* __restrict__ W,
                                               const float* __restrict__ b_enc) {
    const int row = blockIdx.x;
    __shared__ float sae[D_IN];
    __shared__ float vals[CAP];
    __shared__ int   cidx[CAP];
    const int tid = threadIdx.x, lane = tid & 31, wid = tid >> 5;

    for (int i = tid; i < D_IN; i += 256) sae[i] = x[(size_t)row * D_IN + i] - b_dec[i];
    const int nc = g_ncand[row];
    for (int i = tid; i < nc; i += 256) cidx[i] = g_cand[row * CAP + i];
    __syncthreads();

    for (int c = wid; c < nc; c += 8) {
        const int h = cidx[c];
        const float* wr = W + (size_t)h * D_IN;
        float s = 0.f, comp = 0.f;
        for (int j = lane; j < D_IN; j += 32) {
            float p = sae[j] * wr[j];
            float t = s + p;
            comp += (fabsf(s) >= fabsf(p)) ? ((s - t) + p) : ((p - t) + s);
            s = t;
        }
        #pragma unroll
        for (int o = 16; o; o >>= 1) {
            float s2 = __shfl_down_sync(0xffffffffu, s, o);
            float c2 = __shfl_down_sync(0xffffffffu, comp, o);
            float t = s + s2;
            float e = (fabsf(s) >= fabsf(s2)) ? ((s - t) + s2) : ((s2 - t) + s);
            s = t;
            comp = comp + c2 + e;
        }
        if (lane == 0) {
            float v = (s + comp) + b_enc[h];
            vals[c] = (v > 0.f) ? v : 0.f;
        }
    }
    __syncthreads();

    if (wid == 0) {
        for (int t = 0; t < TOPK; t++) {
            float bv = -1.f; int bi = 0x7fffffff; int bc = -1;
            for (int c = lane; c < nc; c += 32) {
                float v = vals[c]; int h = cidx[c];
                if (v > bv || (v == bv && h < bi)) { bv = v; bi = h; bc = c; }
            }
            #pragma unroll
            for (int o = 16; o; o >>= 1) {
                float ov = __shfl_down_sync(0xffffffffu, bv, o);
                int   oi = __shfl_down_sync(0xffffffffu, bi, o);
                int   oc = __shfl_down_sync(0xffffffffu, bc, o);
                if (ov > bv || (ov == bv && oi < bi)) { bv = ov; bi = oi; bc = oc; }
            }
            bv = __shfl_sync(0xffffffffu, bv, 0);
            bi = __shfl_sync(0xffffffffu, bi, 0);
            bc = __shfl_sync(0xffffffffu, bc, 0);
            if (lane == 0) {
                g_topv[row * TOPK + t] = (bc >= 0 && bv > 0.f) ? bv : 0.f;
                g_topi[row * TOPK + t] = (bc >= 0) ? bi : 0;
                if (bc >= 0) vals[bc] = -2.f;
            }
            __syncwarp();
        }
    }
}

// ---------------- decode ----------------
__global__ __launch_bounds__(256) void k_decode(const float* __restrict__ W_dec,
                                                const float* __restrict__ b_dec,
                                                float* __restrict__ out) {
    const int row = blockIdx.x;
    const int tid = threadIdx.x;
    __shared__ float v[TOPK];
    __shared__ int   hi[TOPK];
    if (tid < TOPK) {
        v[tid]  = g_topv[row * TOPK + tid];
        hi[tid] = g_topi[row * TOPK + tid];
    }
    __syncthreads();
    float acc0 = 0.f, acc1 = 0.f, acc2 = 0.f, acc3 = 0.f;
    #pragma unroll 1
    for (int t = 0; t < TOPK; t++) {
        const float* wr = W_dec + (size_t)hi[t] * D_IN;
        const float vt = v[t];
        acc0 += vt * wr[tid];
        acc1 += vt * wr[tid + 256];
        acc2 += vt * wr[tid + 512];
        acc3 += vt * wr[tid + 768];
    }
    float* o = out + (size_t)row * D_IN;
    o[tid]       = acc0 + b_dec[tid];
    o[tid + 256] = acc1 + b_dec[tid + 256];
    o[tid + 512] = acc2 + b_dec[tid + 512];
    o[tid + 768] = acc3 + b_dec[tid + 768];
}

// ---------------- launcher ----------------
extern "C" void kernel_launch(void* const* d_in, const int* in_sizes, int n_in,
                              void* d_out, int out_size) {
    const float* x     = (const float*)d_in[0];
    const float* W_enc = (const float*)d_in[1];
    const float* b_enc = (const float*)d_in[2];
    const float* W_dec = (const float*)d_in[3];
    const float* b_dec = (const float*)d_in[4];
    float* out = (float*)d_out;

    cudaFuncSetAttribute(k_gemm, cudaFuncAttributeMaxDynamicSharedMemorySize, GEMM_SMEM);

    k_convW<<<2048, 256>>>(W_enc);
    k_convX<<<512, 256>>>(x, b_dec);

    dim3 g(HID / BN, B_ROWS / BM);
    k_gemm<<<g, 256, GEMM_SMEM>>>(b_enc);

    k_select<<<B_ROWS, 256>>>();
    k_exact<<<B_ROWS, 256>>>(x, b_dec, W_enc, b_enc);
    k_decode<<<B_ROWS, 256>>>(W_dec, b_dec, out);
}

// round 15
// speedup vs baseline: 1.6216x; 1.6216x over previous
#include <cuda_runtime.h>
#include <cuda_bf16.h>
#include <cstdint>

#define B_ROWS 4096
#define D_IN   1024
#define HID    32768
#define TOPK   32
#define NCAND  48
#define CAP    96

// ---------------- static device scratch ----------------
__device__ __nv_bfloat16 g_Wb[(size_t)HID * D_IN];
__device__ __nv_bfloat16 g_xb[(size_t)B_ROWS * D_IN];
__device__ __align__(16) __nv_bfloat16 g_pre[(size_t)B_ROWS * HID];
__device__ int   g_cand[B_ROWS * CAP];
__device__ int   g_ncand[B_ROWS];
__device__ float g_topv[B_ROWS * TOPK];
__device__ int   g_topi[B_ROWS * TOPK];

__device__ __forceinline__ uint32_t pack_bf16x2(float lo, float hi) {
    uint32_t r;
    asm("cvt.rn.bf16x2.f32 %0, %1, %2;" : "=r"(r) : "f"(hi), "f"(lo));
    return r;
}

// ---------------- converters ----------------
__global__ void k_convW(const float* __restrict__ W) {
    size_t n = (size_t)HID * D_IN / 8;
    const float4* src = reinterpret_cast<const float4*>(W);
    uint4* dst = reinterpret_cast<uint4*>(g_Wb);
    for (size_t i = (size_t)blockIdx.x * blockDim.x + threadIdx.x; i < n;
         i += (size_t)gridDim.x * blockDim.x) {
        float4 a = src[2 * i], b = src[2 * i + 1];
        uint4 o;
        o.x = pack_bf16x2(a.x, a.y);
        o.y = pack_bf16x2(a.z, a.w);
        o.z = pack_bf16x2(b.x, b.y);
        o.w = pack_bf16x2(b.z, b.w);
        dst[i] = o;
    }
}

__global__ void k_convX(const float* __restrict__ x, const float* __restrict__ b_dec) {
    size_t n = (size_t)B_ROWS * D_IN;
    for (size_t i = (size_t)blockIdx.x * blockDim.x + threadIdx.x; i < n;
         i += (size_t)gridDim.x * blockDim.x) {
        int d = (int)(i & (D_IN - 1));
        g_xb[i] = __float2bfloat16(x[i] - b_dec[d]);
    }
}

// ---------------- GEMM: 128x128, BK=32, 3-stage cp.async (round-11) --------
#define BM 128
#define BN 128
#define BK 32
#define KT (D_IN / BK)

__device__ __forceinline__ uint32_t swz32(uint32_t r, uint32_t c) {
    uint32_t pr = r >> 1;
    uint32_t pc = (c + ((r & 1u) << 2)) ^ (pr & 7u);
    return pr * 128u + (pc << 4);
}

__global__ __launch_bounds__(256) void k_gemm(const float* __restrict__ b_enc) {
    __shared__ __align__(16) uint8_t smem[3 * 16384];   // 48 KB

    const int tid  = threadIdx.x;
    const int wid  = tid >> 5;
    const int lane = tid & 31;
    const int bm0  = blockIdx.y * BM;
    const int bn0  = blockIdx.x * BN;
    const int warp_m = (wid >> 2) * 64;
    const int warp_n = (wid & 3) * 32;

    float acc[4][4][4];
    #pragma unroll
    for (int a = 0; a < 4; a++)
        #pragma unroll
        for (int b = 0; b < 4; b++)
            #pragma unroll
            for (int c = 0; c < 4; c++) acc[a][b][c] = 0.f;

    auto issueLoads = [&](int kt, int stage) {
        const __nv_bfloat16* Asrc = g_xb + (size_t)bm0 * D_IN + kt * BK;
        const __nv_bfloat16* Bsrc = g_Wb + (size_t)bn0 * D_IN + kt * BK;
        uint8_t* As = smem + stage * 16384;
        uint8_t* Bs = As + 8192;
        #pragma unroll
        for (int i = 0; i < 2; i++) {
            int id = tid + 256 * i;
            int r = id >> 2, c = id & 3;
            uint32_t da = (uint32_t)__cvta_generic_to_shared(As + swz32(r, c));
            const void* sa = Asrc + (size_t)r * D_IN + c * 8;
            asm volatile("cp.async.cg.shared.global [%0], [%1], 16;\n" :: "r"(da), "l"(sa));
            uint32_t db = (uint32_t)__cvta_generic_to_shared(Bs + swz32(r, c));
            const void* sb = Bsrc + (size_t)r * D_IN + c * 8;
            asm volatile("cp.async.cg.shared.global [%0], [%1], 16;\n" :: "r"(db), "l"(sb));
        }
    };

    auto computeStage = [&](int stage) {
        uint8_t* As = smem + stage * 16384;
        uint8_t* Bs = As + 8192;
        #pragma unroll
        for (int ks = 0; ks < 2; ks++) {
            uint32_t a[4][4], b[2][4];
            #pragma unroll
            for (int im = 0; im < 4; im++) {
                int r = warp_m + im * 16 + (lane & 15);
                int c = ks * 2 + (lane >> 4);
                uint32_t addr = (uint32_t)__cvta_generic_to_shared(As + swz32(r, c));
                asm volatile("ldmatrix.sync.aligned.m8n8.x4.shared.b16 {%0,%1,%2,%3}, [%4];\n"
                             : "=r"(a[im][0]), "=r"(a[im][1]), "=r"(a[im][2]), "=r"(a[im][3])
                             : "r"(addr));
            }
            #pragma unroll
            for (int in2 = 0; in2 < 2; in2++) {
                int r = warp_n + in2 * 16 + (lane & 7) + ((lane & 16) ? 8 : 0);
                int c = ks * 2 + ((lane >> 3) & 1);
                uint32_t addr = (uint32_t)__cvta_generic_to_shared(Bs + swz32(r, c));
                asm volatile("ldmatrix.sync.aligned.m8n8.x4.shared.b16 {%0,%1,%2,%3}, [%4];\n"
                             : "=r"(b[in2][0]), "=r"(b[in2][1]), "=r"(b[in2][2]), "=r"(b[in2][3])
                             : "r"(addr));
            }
            #pragma unroll
            for (int im = 0; im < 4; im++)
                #pragma unroll
                for (int in8 = 0; in8 < 4; in8++) {
                    uint32_t b0 = b[in8 >> 1][(in8 & 1) * 2 + 0];
                    uint32_t b1 = b[in8 >> 1][(in8 & 1) * 2 + 1];
                    float* c4 = acc[im][in8];
                    asm volatile(
                        "mma.sync.aligned.m16n8k16.row.col.f32.bf16.bf16.f32 "
                        "{%0,%1,%2,%3},{%4,%5,%6,%7},{%8,%9},{%0,%1,%2,%3};\n"
                        : "+f"(c4[0]), "+f"(c4[1]), "+f"(c4[2]), "+f"(c4[3])
                        : "r"(a[im][0]), "r"(a[im][1]), "r"(a[im][2]), "r"(a[im][3]),
                          "r"(b0), "r"(b1));
                }
        }
    };

    issueLoads(0, 0);
    asm volatile("cp.async.commit_group;\n" ::: "memory");
    issueLoads(1, 1);
    asm volatile("cp.async.commit_group;\n" ::: "memory");

    for (int kt = 0; kt < KT; kt++) {
        asm volatile("cp.async.wait_group 1;\n" ::: "memory");
        __syncthreads();
        if (kt + 2 < KT) issueLoads(kt + 2, (kt + 2) % 3);
        asm volatile("cp.async.commit_group;\n" ::: "memory");
        computeStage(kt % 3);
    }

    const int r0 = bm0 + warp_m + (lane >> 2);
    const int c0 = bn0 + warp_n + (lane & 3) * 2;
    #pragma unroll
    for (int im = 0; im < 4; im++)
        #pragma unroll
        for (int in8 = 0; in8 < 4; in8++) {
            int r = r0 + im * 16;
            int h = c0 + in8 * 8;
            float be0 = b_enc[h], be1 = b_enc[h + 1];
            float v0 = fmaxf(acc[im][in8][0] + be0, 0.f);
            float v1 = fmaxf(acc[im][in8][1] + be1, 0.f);
            float v2 = fmaxf(acc[im][in8][2] + be0, 0.f);
            float v3 = fmaxf(acc[im][in8][3] + be1, 0.f);
            *reinterpret_cast<uint32_t*>(&g_pre[(size_t)r * HID + h]) = pack_bf16x2(v0, v1);
            *reinterpret_cast<uint32_t*>(&g_pre[(size_t)(r + 8) * HID + h]) = pack_bf16x2(v2, v3);
        }
}

// ------- top-NCAND selection: 12-bit hist + exact 16-bit refinement --------
__global__ __launch_bounds__(256) void k_select() {
    const int row = blockIdx.x;
    const int tid = threadIdx.x, lane = tid & 31, wi = tid >> 5;
    const uint4* kp4 = reinterpret_cast<const uint4*>(g_pre + (size_t)row * HID);
    __shared__ int hist[4096];
    __shared__ int sub[16];
    __shared__ int warpsum[8];
    __shared__ int sB1, sAbove, sThr, sCnt;

    #pragma unroll
    for (int i = 0; i < 16; i++) hist[tid + 256 * i] = 0;
    if (tid < 16) sub[tid] = 0;
    if (tid == 0) { sB1 = -1; sAbove = 0; sThr = 1; sCnt = 0; }
    __syncthreads();

    for (int i = tid; i < HID / 8; i += 256) {
        uint4 u = kp4[i];
        uint32_t ws[4] = {u.x, u.y, u.z, u.w};
        #pragma unroll
        for (int q = 0; q < 4; q++) {
            uint32_t k0 = ws[q] & 0xFFFFu, k1 = ws[q] >> 16;
            if (k0) atomicAdd(&hist[k0 >> 4], 1);
            if (k1) atomicAdd(&hist[k1 >> 4], 1);
        }
    }
    __syncthreads();

    const int base = 4095 - tid * 16;
    int s = 0;
    #pragma unroll
    for (int j = 0; j < 16; j++) s += hist[base - j];
    int inc = s;
    #pragma unroll
    for (int o = 1; o < 32; o <<= 1) {
        int v = __shfl_up_sync(0xffffffffu, inc, o);
        if (lane >= o) inc += v;
    }
    if (lane == 31) warpsum[wi] = inc;
    __syncthreads();
    if (wi == 0) {
        int wsv = (lane < 8) ? warpsum[lane] : 0;
        #pragma unroll
        for (int o = 1; o < 8; o <<= 1) {
            int v = __shfl_up_sync(0xffffffffu, wsv, o);
            if (lane >= o) wsv += v;
        }
        if (lane < 8) warpsum[lane] = wsv;
    }
    __syncthreads();
    const int above0 = inc - s + (wi ? warpsum[wi - 1] : 0);
    if (above0 < NCAND && above0 + s >= NCAND) {
        int cum = above0;
        #pragma unroll
        for (int j = 0; j < 16; j++) {
            int b = base - j;
            int hb = hist[b];
            if (cum + hb >= NCAND) { sB1 = b; sAbove = cum; break; }
            cum += hb;
        }
    }
    __syncthreads();
    const int B1 = sB1;

    if (B1 >= 0) {
        for (int i = tid; i < HID / 8; i += 256) {
            uint4 u = kp4[i];
            uint32_t ws[4] = {u.x, u.y, u.z, u.w};
            #pragma unroll
            for (int q = 0; q < 4; q++) {
                uint32_t k0 = ws[q] & 0xFFFFu, k1 = ws[q] >> 16;
                if ((int)(k0 >> 4) == B1) atomicAdd(&sub[k0 & 15u], 1);
                if ((int)(k1 >> 4) == B1) atomicAdd(&sub[k1 & 15u], 1);
            }
        }
    }
    __syncthreads();
    if (tid == 0 && B1 >= 0) {
        int cum = sAbove;
        for (int c2 = 15; c2 >= 0; c2--) {
            cum += sub[c2];
            if (cum >= NCAND) { sThr = (B1 << 4) | c2; break; }
        }
    }
    __syncthreads();
    const uint32_t thr = (uint32_t)sThr;

    for (int i = tid; i < HID / 8; i += 256) {
        uint4 u = kp4[i];
        uint32_t ws[4] = {u.x, u.y, u.z, u.w};
        #pragma unroll
        for (int q = 0; q < 4; q++) {
            #pragma unroll
            for (int h = 0; h < 2; h++) {
                uint32_t k = h ? (ws[q] >> 16) : (ws[q] & 0xFFFFu);
                if (k >= thr) {
                    int p = atomicAdd(&sCnt, 1);
                    if (p < CAP) g_cand[row * CAP + p] = i * 8 + q * 2 + h;
                }
            }
        }
    }
    __syncthreads();
    if (tid == 0) g_ncand[row] = min(sCnt, CAP);
}

// ------- exact recompute (fp32 compensated, float4 loads) + top-32 ---------
__global__ __launch_bounds__(256) void k_exact(const float* __restrict__ x,
                                               const float* __restrict__ b_dec,
                                               const float* __restrict__ W,
                                               const float* __restrict__ b_enc) {
    const int row = blockIdx.x;
    __shared__ __align__(16) float sae[D_IN];
    __shared__ float vals[CAP];
    __shared__ int   cidx[CAP];
    const int tid = threadIdx.x, lane = tid & 31, wid = tid >> 5;

    {
        const float4* x4 = reinterpret_cast<const float4*>(x + (size_t)row * D_IN);
        const float4* b4 = reinterpret_cast<const float4*>(b_dec);
        float4* s4 = reinterpret_cast<float4*>(sae);
        for (int i = tid; i < D_IN / 4; i += 256) {
            float4 a = x4[i], b = b4[i];
            s4[i] = make_float4(a.x - b.x, a.y - b.y, a.z - b.z, a.w - b.w);
        }
    }
    const int nc = g_ncand[row];
    for (int i = tid; i < nc; i += 256) cidx[i] = g_cand[row * CAP + i];
    __syncthreads();

    for (int c = wid; c < nc; c += 8) {
        const int h = cidx[c];
        const float4* wr4 = reinterpret_cast<const float4*>(W + (size_t)h * D_IN);
        const float4* s4 = reinterpret_cast<const float4*>(sae);
        float s = 0.f, comp = 0.f;
        #pragma unroll 2
        for (int j = lane; j < D_IN / 4; j += 32) {
            float4 w = wr4[j], v = s4[j];
            float p[4] = {v.x * w.x, v.y * w.y, v.z * w.z, v.w * w.w};
            #pragma unroll
            for (int u = 0; u < 4; u++) {
                float t = s + p[u];
                comp += (fabsf(s) >= fabsf(p[u])) ? ((s - t) + p[u]) : ((p[u] - t) + s);
                s = t;
            }
        }
        #pragma unroll
        for (int o = 16; o; o >>= 1) {
            float s2 = __shfl_down_sync(0xffffffffu, s, o);
            float c2 = __shfl_down_sync(0xffffffffu, comp, o);
            float t = s + s2;
            float e = (fabsf(s) >= fabsf(s2)) ? ((s - t) + s2) : ((s2 - t) + s);
            s = t;
            comp = comp + c2 + e;
        }
        if (lane == 0) {
            float v = (s + comp) + b_enc[h];
            vals[c] = (v > 0.f) ? v : 0.f;
        }
    }
    __syncthreads();

    if (wid == 0) {
        for (int t = 0; t < TOPK; t++) {
            float bv = -1.f; int bi = 0x7fffffff; int bc = -1;
            for (int c = lane; c < nc; c += 32) {
                float v = vals[c]; int h = cidx[c];
                if (v > bv || (v == bv && h < bi)) { bv = v; bi = h; bc = c; }
            }
            #pragma unroll
            for (int o = 16; o; o >>= 1) {
                float ov = __shfl_down_sync(0xffffffffu, bv, o);
                int   oi = __shfl_down_sync(0xffffffffu, bi, o);
                int   oc = __shfl_down_sync(0xffffffffu, bc, o);
                if (ov > bv || (ov == bv && oi < bi)) { bv = ov; bi = oi; bc = oc; }
            }
            bv = __shfl_sync(0xffffffffu, bv, 0);
            bi = __shfl_sync(0xffffffffu, bi, 0);
            bc = __shfl_sync(0xffffffffu, bc, 0);
            if (lane == 0) {
                g_topv[row * TOPK + t] = (bc >= 0 && bv > 0.f) ? bv : 0.f;
                g_topi[row * TOPK + t] = (bc >= 0) ? bi : 0;
                if (bc >= 0) vals[bc] = -2.f;
            }
            __syncwarp();
        }
    }
}

// ---------------- decode (float4) ----------------
__global__ __launch_bounds__(256) void k_decode(const float* __restrict__ W_dec,
                                                const float* __restrict__ b_dec,
                                                float* __restrict__ out) {
    const int row = blockIdx.x;
    const int tid = threadIdx.x;
    __shared__ float v[TOPK];
    __shared__ int   hi[TOPK];
    if (tid < TOPK) {
        v[tid]  = g_topv[row * TOPK + tid];
        hi[tid] = g_topi[row * TOPK + tid];
    }
    __syncthreads();
    float4 acc = make_float4(0.f, 0.f, 0.f, 0.f);
    #pragma unroll 1
    for (int t = 0; t < TOPK; t++) {
        const float4* wr = reinterpret_cast<const float4*>(W_dec + (size_t)hi[t] * D_IN);
        const float vt = v[t];
        float4 w = wr[tid];
        acc.x += vt * w.x;
        acc.y += vt * w.y;
        acc.z += vt * w.z;
        acc.w += vt * w.w;
    }
    const float4 bd = reinterpret_cast<const float4*>(b_dec)[tid];
    acc.x += bd.x; acc.y += bd.y; acc.z += bd.z; acc.w += bd.w;
    reinterpret_cast<float4*>(out + (size_t)row * D_IN)[tid] = acc;
}

// ---------------- launcher ----------------
extern "C" void kernel_launch(void* const* d_in, const int* in_sizes, int n_in,
                              void* d_out, int out_size) {
    const float* x     = (const float*)d_in[0];
    const float* W_enc = (const float*)d_in[1];
    const float* b_enc = (const float*)d_in[2];
    const float* W_dec = (const float*)d_in[3];
    const float* b_dec = (const float*)d_in[4];
    float* out = (float*)d_out;

    k_convW<<<2048, 256>>>(W_enc);
    k_convX<<<512, 256>>>(x, b_dec);

    dim3 g(HID / BN, B_ROWS / BM);
    k_gemm<<<g, 256>>>(b_enc);

    k_select<<<B_ROWS, 256>>>();
    k_exact<<<B_ROWS, 256>>>(x, b_dec, W_enc, b_enc);
    k_decode<<<B_ROWS, 256>>>(W_dec, b_dec, out);
}

// round 16
// speedup vs baseline: 1.6423x; 1.0128x over previous
#include <cuda_runtime.h>
#include <cuda_bf16.h>
#include <cstdint>

#define B_ROWS 4096
#define D_IN   1024
#define HID    32768
#define TOPK   32
#define NCAND  48
#define CAP    96
#define NBLK   (HID / 128)   // 256 column blocks per row

// ---------------- static device scratch ----------------
__device__ __nv_bfloat16 g_Wb[(size_t)HID * D_IN];
__device__ __nv_bfloat16 g_xb[(size_t)B_ROWS * D_IN];
__device__ __align__(16) __nv_bfloat16 g_pre[(size_t)B_ROWS * HID];
__device__ int   g_bmax[(size_t)B_ROWS * NBLK];   // per-(row, col-block) max bf16 code
__device__ int   g_cand[B_ROWS * CAP];
__device__ int   g_ncand[B_ROWS];
__device__ float g_topv[B_ROWS * TOPK];
__device__ int   g_topi[B_ROWS * TOPK];

__device__ __forceinline__ uint32_t pack_bf16x2(float lo, float hi) {
    uint32_t r;
    asm("cvt.rn.bf16x2.f32 %0, %1, %2;" : "=r"(r) : "f"(hi), "f"(lo));
    return r;
}

// ---------------- converters ----------------
__global__ void k_convW(const float* __restrict__ W) {
    size_t n = (size_t)HID * D_IN / 8;
    const float4* src = reinterpret_cast<const float4*>(W);
    uint4* dst = reinterpret_cast<uint4*>(g_Wb);
    for (size_t i = (size_t)blockIdx.x * blockDim.x + threadIdx.x; i < n;
         i += (size_t)gridDim.x * blockDim.x) {
        float4 a = src[2 * i], b = src[2 * i + 1];
        uint4 o;
        o.x = pack_bf16x2(a.x, a.y);
        o.y = pack_bf16x2(a.z, a.w);
        o.z = pack_bf16x2(b.x, b.y);
        o.w = pack_bf16x2(b.z, b.w);
        dst[i] = o;
    }
}

__global__ void k_convX(const float* __restrict__ x, const float* __restrict__ b_dec) {
    size_t n = (size_t)B_ROWS * D_IN;
    for (size_t i = (size_t)blockIdx.x * blockDim.x + threadIdx.x; i < n;
         i += (size_t)gridDim.x * blockDim.x) {
        int d = (int)(i & (D_IN - 1));
        g_xb[i] = __float2bfloat16(x[i] - b_dec[d]);
    }
}

// ---------------- GEMM: 128x128, BK=32, 3-stage cp.async + block-max ------
#define BM 128
#define BN 128
#define BK 32
#define KT (D_IN / BK)
#define GEMM_SMEM (3 * 16384 + 512)   // stages + 128-int bmax

__device__ __forceinline__ uint32_t swz32(uint32_t r, uint32_t c) {
    uint32_t pr = r >> 1;
    uint32_t pc = (c + ((r & 1u) << 2)) ^ (pr & 7u);
    return pr * 128u + (pc << 4);
}

__global__ __launch_bounds__(256) void k_gemm(const float* __restrict__ b_enc) {
    extern __shared__ __align__(16) uint8_t smem[];
    int* s_bmax = reinterpret_cast<int*>(smem + 3 * 16384);

    const int tid  = threadIdx.x;
    const int wid  = tid >> 5;
    const int lane = tid & 31;
    const int bm0  = blockIdx.y * BM;
    const int bn0  = blockIdx.x * BN;
    const int warp_m = (wid >> 2) * 64;
    const int warp_n = (wid & 3) * 32;

    if (tid < 128) s_bmax[tid] = 0;

    float acc[4][4][4];
    #pragma unroll
    for (int a = 0; a < 4; a++)
        #pragma unroll
        for (int b = 0; b < 4; b++)
            #pragma unroll
            for (int c = 0; c < 4; c++) acc[a][b][c] = 0.f;

    auto issueLoads = [&](int kt, int stage) {
        const __nv_bfloat16* Asrc = g_xb + (size_t)bm0 * D_IN + kt * BK;
        const __nv_bfloat16* Bsrc = g_Wb + (size_t)bn0 * D_IN + kt * BK;
        uint8_t* As = smem + stage * 16384;
        uint8_t* Bs = As + 8192;
        #pragma unroll
        for (int i = 0; i < 2; i++) {
            int id = tid + 256 * i;
            int r = id >> 2, c = id & 3;
            uint32_t da = (uint32_t)__cvta_generic_to_shared(As + swz32(r, c));
            const void* sa = Asrc + (size_t)r * D_IN + c * 8;
            asm volatile("cp.async.cg.shared.global [%0], [%1], 16;\n" :: "r"(da), "l"(sa));
            uint32_t db = (uint32_t)__cvta_generic_to_shared(Bs + swz32(r, c));
            const void* sb = Bsrc + (size_t)r * D_IN + c * 8;
            asm volatile("cp.async.cg.shared.global [%0], [%1], 16;\n" :: "r"(db), "l"(sb));
        }
    };

    auto computeStage = [&](int stage) {
        uint8_t* As = smem + stage * 16384;
        uint8_t* Bs = As + 8192;
        #pragma unroll
        for (int ks = 0; ks < 2; ks++) {
            uint32_t a[4][4], b[2][4];
            #pragma unroll
            for (int im = 0; im < 4; im++) {
                int r = warp_m + im * 16 + (lane & 15);
                int c = ks * 2 + (lane >> 4);
                uint32_t addr = (uint32_t)__cvta_generic_to_shared(As + swz32(r, c));
                asm volatile("ldmatrix.sync.aligned.m8n8.x4.shared.b16 {%0,%1,%2,%3}, [%4];\n"
                             : "=r"(a[im][0]), "=r"(a[im][1]), "=r"(a[im][2]), "=r"(a[im][3])
                             : "r"(addr));
            }
            #pragma unroll
            for (int in2 = 0; in2 < 2; in2++) {
                int r = warp_n + in2 * 16 + (lane & 7) + ((lane & 16) ? 8 : 0);
                int c = ks * 2 + ((lane >> 3) & 1);
                uint32_t addr = (uint32_t)__cvta_generic_to_shared(Bs + swz32(r, c));
                asm volatile("ldmatrix.sync.aligned.m8n8.x4.shared.b16 {%0,%1,%2,%3}, [%4];\n"
                             : "=r"(b[in2][0]), "=r"(b[in2][1]), "=r"(b[in2][2]), "=r"(b[in2][3])
                             : "r"(addr));
            }
            #pragma unroll
            for (int im = 0; im < 4; im++)
                #pragma unroll
                for (int in8 = 0; in8 < 4; in8++) {
                    uint32_t b0 = b[in8 >> 1][(in8 & 1) * 2 + 0];
                    uint32_t b1 = b[in8 >> 1][(in8 & 1) * 2 + 1];
                    float* c4 = acc[im][in8];
                    asm volatile(
                        "mma.sync.aligned.m16n8k16.row.col.f32.bf16.bf16.f32 "
                        "{%0,%1,%2,%3},{%4,%5,%6,%7},{%8,%9},{%0,%1,%2,%3};\n"
                        : "+f"(c4[0]), "+f"(c4[1]), "+f"(c4[2]), "+f"(c4[3])
                        : "r"(a[im][0]), "r"(a[im][1]), "r"(a[im][2]), "r"(a[im][3]),
                          "r"(b0), "r"(b1));
                }
        }
    };

    issueLoads(0, 0);
    asm volatile("cp.async.commit_group;\n" ::: "memory");
    issueLoads(1, 1);
    asm volatile("cp.async.commit_group;\n" ::: "memory");

    for (int kt = 0; kt < KT; kt++) {
        asm volatile("cp.async.wait_group 1;\n" ::: "memory");
        __syncthreads();
        if (kt + 2 < KT) issueLoads(kt + 2, (kt + 2) % 3);
        asm volatile("cp.async.commit_group;\n" ::: "memory");
        computeStage(kt % 3);
    }

    const int rloc0 = warp_m + (lane >> 2);
    const int r0 = bm0 + rloc0;
    const int c0 = bn0 + warp_n + (lane & 3) * 2;
    #pragma unroll
    for (int im = 0; im < 4; im++) {
        uint32_t mA = 0, mB = 0;
        #pragma unroll
        for (int in8 = 0; in8 < 4; in8++) {
            int r = r0 + im * 16;
            int h = c0 + in8 * 8;
            float be0 = b_enc[h], be1 = b_enc[h + 1];
            float v0 = fmaxf(acc[im][in8][0] + be0, 0.f);
            float v1 = fmaxf(acc[im][in8][1] + be1, 0.f);
            float v2 = fmaxf(acc[im][in8][2] + be0, 0.f);
            float v3 = fmaxf(acc[im][in8][3] + be1, 0.f);
            uint32_t pA = pack_bf16x2(v0, v1);
            uint32_t pB = pack_bf16x2(v2, v3);
            *reinterpret_cast<uint32_t*>(&g_pre[(size_t)r * HID + h]) = pA;
            *reinterpret_cast<uint32_t*>(&g_pre[(size_t)(r + 8) * HID + h]) = pB;
            mA = max(mA, max(pA & 0xFFFFu, pA >> 16));
            mB = max(mB, max(pB & 0xFFFFu, pB >> 16));
        }
        atomicMax(&s_bmax[rloc0 + im * 16], (int)mA);
        atomicMax(&s_bmax[rloc0 + im * 16 + 8], (int)mB);
    }
    __syncthreads();
    if (tid < 128)
        g_bmax[(size_t)(bm0 + tid) * NBLK + blockIdx.x] = s_bmax[tid];
}

// ------- selection: block-max pruning + 12-bit hist + 16-bit refinement ----
__global__ __launch_bounds__(256) void k_select() {
    const int row = blockIdx.x;
    const int tid = threadIdx.x, lane = tid & 31, wi = tid >> 5;
    const uint4* kp4 = reinterpret_cast<const uint4*>(g_pre + (size_t)row * HID);
    __shared__ int hist[4096];
    __shared__ int mx[NBLK];
    __shared__ int list[NBLK];
    __shared__ int sub[16];
    __shared__ int warpsum[8];
    __shared__ int sBlkB1, sB1, sAbove, sThr, sCnt, sNK;

    #pragma unroll
    for (int i = 0; i < 16; i++) hist[tid + 256 * i] = 0;
    mx[tid] = g_bmax[(size_t)row * NBLK + tid];
    if (tid < 16) sub[tid] = 0;
    if (tid == 0) { sBlkB1 = -1; sB1 = -1; sAbove = 0; sThr = 1; sCnt = 0; sNK = 0; }
    __syncthreads();

    // stage A: histogram of block maxes, find coarse bucket of 48th-largest
    { int m = mx[tid]; if (m) atomicAdd(&hist[m >> 4], 1); }
    __syncthreads();

    const int base = 4095 - tid * 16;
    {
        int s = 0;
        #pragma unroll
        for (int j = 0; j < 16; j++) s += hist[base - j];
        int inc = s;
        #pragma unroll
        for (int o = 1; o < 32; o <<= 1) {
            int v = __shfl_up_sync(0xffffffffu, inc, o);
            if (lane >= o) inc += v;
        }
        if (lane == 31) warpsum[wi] = inc;
        __syncthreads();
        if (wi == 0) {
            int wsv = (lane < 8) ? warpsum[lane] : 0;
            #pragma unroll
            for (int o = 1; o < 8; o <<= 1) {
                int v = __shfl_up_sync(0xffffffffu, wsv, o);
                if (lane >= o) wsv += v;
            }
            if (lane < 8) warpsum[lane] = wsv;
        }
        __syncthreads();
        int above = inc - s + (wi ? warpsum[wi - 1] : 0);
        if (above < NCAND && above + s >= NCAND) {
            int cum = above;
            #pragma unroll
            for (int j = 0; j < 16; j++) {
                int hb = hist[base - j];
                if (cum + hb >= NCAND) { sBlkB1 = base - j; break; }
                cum += hb;
            }
        }
    }
    __syncthreads();
    const int tblk = (sBlkB1 >= 0) ? (sBlkB1 << 4) : 0;

    // stage B: build kept-block list (zero-max blocks never contain candidates)
    if (mx[tid] >= tblk && mx[tid] > 0) {
        int p = atomicAdd(&sNK, 1);
        list[p] = tid;
    }
    // clear hist for value histogram
    __syncthreads();
    #pragma unroll
    for (int i = 0; i < 16; i++) hist[tid + 256 * i] = 0;
    __syncthreads();
    const int nk = sNK;
    const int tot = nk * 16;

    // stage C: value histogram over kept blocks (skip zeros)
    for (int i = tid; i < tot; i += 256) {
        uint4 u = kp4[list[i >> 4] * 16 + (i & 15)];
        uint32_t ws[4] = {u.x, u.y, u.z, u.w};
        #pragma unroll
        for (int q = 0; q < 4; q++) {
            uint32_t k0 = ws[q] & 0xFFFFu, k1 = ws[q] >> 16;
            if (k0) atomicAdd(&hist[k0 >> 4], 1);
            if (k1) atomicAdd(&hist[k1 >> 4], 1);
        }
    }
    __syncthreads();

    {
        int s = 0;
        #pragma unroll
        for (int j = 0; j < 16; j++) s += hist[base - j];
        int inc = s;
        #pragma unroll
        for (int o = 1; o < 32; o <<= 1) {
            int v = __shfl_up_sync(0xffffffffu, inc, o);
            if (lane >= o) inc += v;
        }
        if (lane == 31) warpsum[wi] = inc;
        __syncthreads();
        if (wi == 0) {
            int wsv = (lane < 8) ? warpsum[lane] : 0;
            #pragma unroll
            for (int o = 1; o < 8; o <<= 1) {
                int v = __shfl_up_sync(0xffffffffu, wsv, o);
                if (lane >= o) wsv += v;
            }
            if (lane < 8) warpsum[lane] = wsv;
        }
        __syncthreads();
        int above = inc - s + (wi ? warpsum[wi - 1] : 0);
        if (above < NCAND && above + s >= NCAND) {
            int cum = above;
            #pragma unroll
            for (int j = 0; j < 16; j++) {
                int b = base - j;
                int hb = hist[b];
                if (cum + hb >= NCAND) { sB1 = b; sAbove = cum; break; }
                cum += hb;
            }
        }
    }
    __syncthreads();
    const int B1 = sB1;

    // stage D: 16-way refinement inside coarse bucket (kept blocks only)
    if (B1 >= 0) {
        for (int i = tid; i < tot; i += 256) {
            uint4 u = kp4[list[i >> 4] * 16 + (i & 15)];
            uint32_t ws[4] = {u.x, u.y, u.z, u.w};
            #pragma unroll
            for (int q = 0; q < 4; q++) {
                uint32_t k0 = ws[q] & 0xFFFFu, k1 = ws[q] >> 16;
                if ((int)(k0 >> 4) == B1) atomicAdd(&sub[k0 & 15u], 1);
                if ((int)(k1 >> 4) == B1) atomicAdd(&sub[k1 & 15u], 1);
            }
        }
    }
    __syncthreads();
    if (tid == 0 && B1 >= 0) {
        int cum = sAbove;
        for (int c2 = 15; c2 >= 0; c2--) {
            cum += sub[c2];
            if (cum >= NCAND) { sThr = (B1 << 4) | c2; break; }
        }
    }
    __syncthreads();
    const uint32_t thr = (uint32_t)sThr;

    // stage E: collect candidate indices from kept blocks
    for (int i = tid; i < tot; i += 256) {
        const int j = list[i >> 4];
        const int off = i & 15;
        uint4 u = kp4[j * 16 + off];
        uint32_t ws[4] = {u.x, u.y, u.z, u.w};
        #pragma unroll
        for (int q = 0; q < 4; q++) {
            #pragma unroll
            for (int h = 0; h < 2; h++) {
                uint32_t k = h ? (ws[q] >> 16) : (ws[q] & 0xFFFFu);
                if (k >= thr) {
                    int p = atomicAdd(&sCnt, 1);
                    if (p < CAP) g_cand[row * CAP + p] = j * 128 + off * 8 + q * 2 + h;
                }
            }
        }
    }
    __syncthreads();
    if (tid == 0) g_ncand[row] = min(sCnt, CAP);
}

// ------- exact recompute (fp32 compensated, float4 loads) + top-32 ---------
__global__ __launch_bounds__(256) void k_exact(const float* __restrict__ x,
                                               const float* __restrict__ b_dec,
                                               const float* __restrict__ W,
                                               const float* __restrict__ b_enc) {
    const int row = blockIdx.x;
    __shared__ __align__(16) float sae[D_IN];
    __shared__ float vals[CAP];
    __shared__ int   cidx[CAP];
    const int tid = threadIdx.x, lane = tid & 31, wid = tid >> 5;

    {
        const float4* x4 = reinterpret_cast<const float4*>(x + (size_t)row * D_IN);
        const float4* b4 = reinterpret_cast<const float4*>(b_dec);
        float4* s4 = reinterpret_cast<float4*>(sae);
        for (int i = tid; i < D_IN / 4; i += 256) {
            float4 a = x4[i], b = b4[i];
            s4[i] = make_float4(a.x - b.x, a.y - b.y, a.z - b.z, a.w - b.w);
        }
    }
    const int nc = g_ncand[row];
    for (int i = tid; i < nc; i += 256) cidx[i] = g_cand[row * CAP + i];
    __syncthreads();

    for (int c = wid; c < nc; c += 8) {
        const int h = cidx[c];
        const float4* wr4 = reinterpret_cast<const float4*>(W + (size_t)h * D_IN);
        const float4* s4 = reinterpret_cast<const float4*>(sae);
        float s = 0.f, comp = 0.f;
        #pragma unroll 2
        for (int j = lane; j < D_IN / 4; j += 32) {
            float4 w = wr4[j], v = s4[j];
            float p[4] = {v.x * w.x, v.y * w.y, v.z * w.z, v.w * w.w};
            #pragma unroll
            for (int u = 0; u < 4; u++) {
                float t = s + p[u];
                comp += (fabsf(s) >= fabsf(p[u])) ? ((s - t) + p[u]) : ((p[u] - t) + s);
                s = t;
            }
        }
        #pragma unroll
        for (int o = 16; o; o >>= 1) {
            float s2 = __shfl_down_sync(0xffffffffu, s, o);
            float c2 = __shfl_down_sync(0xffffffffu, comp, o);
            float t = s + s2;
            float e = (fabsf(s) >= fabsf(s2)) ? ((s - t) + s2) : ((s2 - t) + s);
            s = t;
            comp = comp + c2 + e;
        }
        if (lane == 0) {
            float v = (s + comp) + b_enc[h];
            vals[c] = (v > 0.f) ? v : 0.f;
        }
    }
    __syncthreads();

    if (wid == 0) {
        for (int t = 0; t < TOPK; t++) {
            float bv = -1.f; int bi = 0x7fffffff; int bc = -1;
            for (int c = lane; c < nc; c += 32) {
                float v = vals[c]; int h = cidx[c];
                if (v > bv || (v == bv && h < bi)) { bv = v; bi = h; bc = c; }
            }
            #pragma unroll
            for (int o = 16; o; o >>= 1) {
                float ov = __shfl_down_sync(0xffffffffu, bv, o);
                int   oi = __shfl_down_sync(0xffffffffu, bi, o);
                int   oc = __shfl_down_sync(0xffffffffu, bc, o);
                if (ov > bv || (ov == bv && oi < bi)) { bv = ov; bi = oi; bc = oc; }
            }
            bv = __shfl_sync(0xffffffffu, bv, 0);
            bi = __shfl_sync(0xffffffffu, bi, 0);
            bc = __shfl_sync(0xffffffffu, bc, 0);
            if (lane == 0) {
                g_topv[row * TOPK + t] = (bc >= 0 && bv > 0.f) ? bv : 0.f;
                g_topi[row * TOPK + t] = (bc >= 0) ? bi : 0;
                if (bc >= 0) vals[bc] = -2.f;
            }
            __syncwarp();
        }
    }
}

// ---------------- decode (float4) ----------------
__global__ __launch_bounds__(256) void k_decode(const float* __restrict__ W_dec,
                                                const float* __restrict__ b_dec,
                                                float* __restrict__ out) {
    const int row = blockIdx.x;
    const int tid = threadIdx.x;
    __shared__ float v[TOPK];
    __shared__ int   hi[TOPK];
    if (tid < TOPK) {
        v[tid]  = g_topv[row * TOPK + tid];
        hi[tid] = g_topi[row * TOPK + tid];
    }
    __syncthreads();
    float4 acc = make_float4(0.f, 0.f, 0.f, 0.f);
    #pragma unroll 1
    for (int t = 0; t < TOPK; t++) {
        const float4* wr = reinterpret_cast<const float4*>(W_dec + (size_t)hi[t] * D_IN);
        const float vt = v[t];
        float4 w = wr[tid];
        acc.x += vt * w.x;
        acc.y += vt * w.y;
        acc.z += vt * w.z;
        acc.w += vt * w.w;
    }
    const float4 bd = reinterpret_cast<const float4*>(b_dec)[tid];
    acc.x += bd.x; acc.y += bd.y; acc.z += bd.z; acc.w += bd.w;
    reinterpret_cast<float4*>(out + (size_t)row * D_IN)[tid] = acc;
}

// ---------------- launcher ----------------
extern "C" void kernel_launch(void* const* d_in, const int* in_sizes, int n_in,
                              void* d_out, int out_size) {
    const float* x     = (const float*)d_in[0];
    const float* W_enc = (const float*)d_in[1];
    const float* b_enc = (const float*)d_in[2];
    const float* W_dec = (const float*)d_in[3];
    const float* b_dec = (const float*)d_in[4];
    float* out = (float*)d_out;

    cudaFuncSetAttribute(k_gemm, cudaFuncAttributeMaxDynamicSharedMemorySize, GEMM_SMEM);

    k_convW<<<2048, 256>>>(W_enc);
    k_convX<<<512, 256>>>(x, b_dec);

    dim3 g(HID / BN, B_ROWS / BM);
    k_gemm<<<g, 256, GEMM_SMEM>>>(b_enc);

    k_select<<<B_ROWS, 256>>>();
    k_exact<<<B_ROWS, 256>>>(x, b_dec, W_enc, b_enc);
    k_decode<<<B_ROWS, 256>>>(W_dec, b_dec, out);
}

// round 17
// speedup vs baseline: 1.7709x; 1.0783x over previous
#include <cuda_runtime.h>
#include <cuda_bf16.h>
#include <cstdint>

#define B_ROWS 4096
#define D_IN   1024
#define HID    32768
#define TOPK   32
#define NCAND  48
#define CAP    96
#define NBLK   (HID / 128)   // 256 column blocks per row

// ---------------- static device scratch ----------------
__device__ __nv_bfloat16 g_Wb[(size_t)HID * D_IN];
__device__ __nv_bfloat16 g_xb[(size_t)B_ROWS * D_IN];
__device__ __align__(16) __nv_bfloat16 g_pre[(size_t)B_ROWS * HID];
__device__ int   g_bmax[(size_t)B_ROWS * NBLK];
__device__ int   g_cand[B_ROWS * CAP];
__device__ int   g_ncand[B_ROWS];
__device__ float g_topv[B_ROWS * TOPK];
__device__ int   g_topi[B_ROWS * TOPK];

__device__ __forceinline__ uint32_t pack_bf16x2(float lo, float hi) {
    uint32_t r;
    asm("cvt.rn.bf16x2.f32 %0, %1, %2;" : "=r"(r) : "f"(hi), "f"(lo));
    return r;
}

// ---------------- converters ----------------
__global__ void k_convW(const float* __restrict__ W) {
    size_t n = (size_t)HID * D_IN / 8;
    const float4* src = reinterpret_cast<const float4*>(W);
    uint4* dst = reinterpret_cast<uint4*>(g_Wb);
    for (size_t i = (size_t)blockIdx.x * blockDim.x + threadIdx.x; i < n;
         i += (size_t)gridDim.x * blockDim.x) {
        float4 a = src[2 * i], b = src[2 * i + 1];
        uint4 o;
        o.x = pack_bf16x2(a.x, a.y);
        o.y = pack_bf16x2(a.z, a.w);
        o.z = pack_bf16x2(b.x, b.y);
        o.w = pack_bf16x2(b.z, b.w);
        dst[i] = o;
    }
}

__global__ void k_convX(const float* __restrict__ x, const float* __restrict__ b_dec) {
    size_t n = (size_t)B_ROWS * D_IN;
    for (size_t i = (size_t)blockIdx.x * blockDim.x + threadIdx.x; i < n;
         i += (size_t)gridDim.x * blockDim.x) {
        int d = (int)(i & (D_IN - 1));
        g_xb[i] = __float2bfloat16(x[i] - b_dec[d]);
    }
}

// ------ GEMM: 128x128, BK=64, 3-stage cp.async (96KB dyn), block-max ------
#define BM 128
#define BN 128
#define BK 64
#define KT (D_IN / BK)          // 16 iterations
#define TSTG 32768              // A 16KB + B 16KB per stage
#define GEMM_SMEM (3 * TSTG + 512)

// 128B-wide row swizzle: row r, 16B-chunk c (0..7)
__device__ __forceinline__ uint32_t swz64(uint32_t r, uint32_t c) {
    return r * 128u + ((c ^ (r & 7u)) << 4);
}

__global__ __launch_bounds__(256) void k_gemm(const float* __restrict__ b_enc) {
    extern __shared__ __align__(16) uint8_t smem[];
    int* s_bmax = reinterpret_cast<int*>(smem + 3 * TSTG);

    const int tid  = threadIdx.x;
    const int wid  = tid >> 5;
    const int lane = tid & 31;
    const int bm0  = blockIdx.y * BM;
    const int bn0  = blockIdx.x * BN;
    const int warp_m = (wid >> 2) * 64;
    const int warp_n = (wid & 3) * 32;

    if (tid < 128) s_bmax[tid] = 0;

    float acc[4][4][4];
    #pragma unroll
    for (int a = 0; a < 4; a++)
        #pragma unroll
        for (int b = 0; b < 4; b++)
            #pragma unroll
            for (int c = 0; c < 4; c++) acc[a][b][c] = 0.f;

    auto issueLoads = [&](int kt, int stage) {
        const __nv_bfloat16* Asrc = g_xb + (size_t)bm0 * D_IN + kt * BK;
        const __nv_bfloat16* Bsrc = g_Wb + (size_t)bn0 * D_IN + kt * BK;
        uint8_t* As = smem + stage * TSTG;
        uint8_t* Bs = As + 16384;
        #pragma unroll
        for (int i = 0; i < 4; i++) {        // A: 128 rows x 8 chunks = 1024
            int id = tid + 256 * i;
            int r = id >> 3, c = id & 7;
            uint32_t da = (uint32_t)__cvta_generic_to_shared(As + swz64(r, c));
            const void* sa = Asrc + (size_t)r * D_IN + c * 8;
            asm volatile("cp.async.cg.shared.global [%0], [%1], 16;\n" :: "r"(da), "l"(sa));
        }
        #pragma unroll
        for (int i = 0; i < 4; i++) {        // B: 128 rows x 8 chunks = 1024
            int id = tid + 256 * i;
            int r = id >> 3, c = id & 7;
            uint32_t db = (uint32_t)__cvta_generic_to_shared(Bs + swz64(r, c));
            const void* sb = Bsrc + (size_t)r * D_IN + c * 8;
            asm volatile("cp.async.cg.shared.global [%0], [%1], 16;\n" :: "r"(db), "l"(sb));
        }
    };

    auto computeStage = [&](int stage) {
        uint8_t* As = smem + stage * TSTG;
        uint8_t* Bs = As + 16384;
        #pragma unroll
        for (int ks = 0; ks < 4; ks++) {
            uint32_t a[4][4], b[2][4];
            #pragma unroll
            for (int im = 0; im < 4; im++) {
                int r = warp_m + im * 16 + (lane & 15);
                int c = ks * 2 + (lane >> 4);
                uint32_t addr = (uint32_t)__cvta_generic_to_shared(As + swz64(r, c));
                asm volatile("ldmatrix.sync.aligned.m8n8.x4.shared.b16 {%0,%1,%2,%3}, [%4];\n"
                             : "=r"(a[im][0]), "=r"(a[im][1]), "=r"(a[im][2]), "=r"(a[im][3])
                             : "r"(addr));
            }
            #pragma unroll
            for (int in2 = 0; in2 < 2; in2++) {
                int r = warp_n + in2 * 16 + (lane & 7) + ((lane & 16) ? 8 : 0);
                int c = ks * 2 + ((lane >> 3) & 1);
                uint32_t addr = (uint32_t)__cvta_generic_to_shared(Bs + swz64(r, c));
                asm volatile("ldmatrix.sync.aligned.m8n8.x4.shared.b16 {%0,%1,%2,%3}, [%4];\n"
                             : "=r"(b[in2][0]), "=r"(b[in2][1]), "=r"(b[in2][2]), "=r"(b[in2][3])
                             : "r"(addr));
            }
            #pragma unroll
            for (int im = 0; im < 4; im++)
                #pragma unroll
                for (int in8 = 0; in8 < 4; in8++) {
                    uint32_t b0 = b[in8 >> 1][(in8 & 1) * 2 + 0];
                    uint32_t b1 = b[in8 >> 1][(in8 & 1) * 2 + 1];
                    float* c4 = acc[im][in8];
                    asm volatile(
                        "mma.sync.aligned.m16n8k16.row.col.f32.bf16.bf16.f32 "
                        "{%0,%1,%2,%3},{%4,%5,%6,%7},{%8,%9},{%0,%1,%2,%3};\n"
                        : "+f"(c4[0]), "+f"(c4[1]), "+f"(c4[2]), "+f"(c4[3])
                        : "r"(a[im][0]), "r"(a[im][1]), "r"(a[im][2]), "r"(a[im][3]),
                          "r"(b0), "r"(b1));
                }
        }
    };

    issueLoads(0, 0);
    asm volatile("cp.async.commit_group;\n" ::: "memory");
    issueLoads(1, 1);
    asm volatile("cp.async.commit_group;\n" ::: "memory");

    for (int kt = 0; kt < KT; kt++) {
        asm volatile("cp.async.wait_group 1;\n" ::: "memory");
        __syncthreads();
        if (kt + 2 < KT) issueLoads(kt + 2, (kt + 2) % 3);
        asm volatile("cp.async.commit_group;\n" ::: "memory");
        computeStage(kt % 3);
    }

    const int rloc0 = warp_m + (lane >> 2);
    const int r0 = bm0 + rloc0;
    const int c0 = bn0 + warp_n + (lane & 3) * 2;
    #pragma unroll
    for (int im = 0; im < 4; im++) {
        uint32_t mA = 0, mB = 0;
        #pragma unroll
        for (int in8 = 0; in8 < 4; in8++) {
            int r = r0 + im * 16;
            int h = c0 + in8 * 8;
            float be0 = b_enc[h], be1 = b_enc[h + 1];
            float v0 = fmaxf(acc[im][in8][0] + be0, 0.f);
            float v1 = fmaxf(acc[im][in8][1] + be1, 0.f);
            float v2 = fmaxf(acc[im][in8][2] + be0, 0.f);
            float v3 = fmaxf(acc[im][in8][3] + be1, 0.f);
            uint32_t pA = pack_bf16x2(v0, v1);
            uint32_t pB = pack_bf16x2(v2, v3);
            *reinterpret_cast<uint32_t*>(&g_pre[(size_t)r * HID + h]) = pA;
            *reinterpret_cast<uint32_t*>(&g_pre[(size_t)(r + 8) * HID + h]) = pB;
            mA = max(mA, max(pA & 0xFFFFu, pA >> 16));
            mB = max(mB, max(pB & 0xFFFFu, pB >> 16));
        }
        atomicMax(&s_bmax[rloc0 + im * 16], (int)mA);
        atomicMax(&s_bmax[rloc0 + im * 16 + 8], (int)mB);
    }
    __syncthreads();
    if (tid < 128)
        g_bmax[(size_t)(bm0 + tid) * NBLK + blockIdx.x] = s_bmax[tid];
}

// ------- selection: block-max pruning + 12-bit hist + 16-bit refinement ----
__global__ __launch_bounds__(256) void k_select() {
    const int row = blockIdx.x;
    const int tid = threadIdx.x, lane = tid & 31, wi = tid >> 5;
    const uint4* kp4 = reinterpret_cast<const uint4*>(g_pre + (size_t)row * HID);
    __shared__ int hist[4096];
    __shared__ int mx[NBLK];
    __shared__ int list[NBLK];
    __shared__ int sub[16];
    __shared__ int warpsum[8];
    __shared__ int sBlkB1, sB1, sAbove, sThr, sCnt, sNK;

    #pragma unroll
    for (int i = 0; i < 16; i++) hist[tid + 256 * i] = 0;
    mx[tid] = g_bmax[(size_t)row * NBLK + tid];
    if (tid < 16) sub[tid] = 0;
    if (tid == 0) { sBlkB1 = -1; sB1 = -1; sAbove = 0; sThr = 1; sCnt = 0; sNK = 0; }
    __syncthreads();

    { int m = mx[tid]; if (m) atomicAdd(&hist[m >> 4], 1); }
    __syncthreads();

    const int base = 4095 - tid * 16;
    {
        int s = 0;
        #pragma unroll
        for (int j = 0; j < 16; j++) s += hist[base - j];
        int inc = s;
        #pragma unroll
        for (int o = 1; o < 32; o <<= 1) {
            int v = __shfl_up_sync(0xffffffffu, inc, o);
            if (lane >= o) inc += v;
        }
        if (lane == 31) warpsum[wi] = inc;
        __syncthreads();
        if (wi == 0) {
            int wsv = (lane < 8) ? warpsum[lane] : 0;
            #pragma unroll
            for (int o = 1; o < 8; o <<= 1) {
                int v = __shfl_up_sync(0xffffffffu, wsv, o);
                if (lane >= o) wsv += v;
            }
            if (lane < 8) warpsum[lane] = wsv;
        }
        __syncthreads();
        int above = inc - s + (wi ? warpsum[wi - 1] : 0);
        if (above < NCAND && above + s >= NCAND) {
            int cum = above;
            #pragma unroll
            for (int j = 0; j < 16; j++) {
                int hb = hist[base - j];
                if (cum + hb >= NCAND) { sBlkB1 = base - j; break; }
                cum += hb;
            }
        }
    }
    __syncthreads();
    const int tblk = (sBlkB1 >= 0) ? (sBlkB1 << 4) : 0;

    if (mx[tid] >= tblk && mx[tid] > 0) {
        int p = atomicAdd(&sNK, 1);
        list[p] = tid;
    }
    __syncthreads();
    #pragma unroll
    for (int i = 0; i < 16; i++) hist[tid + 256 * i] = 0;
    __syncthreads();
    const int nk = sNK;
    const int tot = nk * 16;

    for (int i = tid; i < tot; i += 256) {
        uint4 u = kp4[list[i >> 4] * 16 + (i & 15)];
        uint32_t ws[4] = {u.x, u.y, u.z, u.w};
        #pragma unroll
        for (int q = 0; q < 4; q++) {
            uint32_t k0 = ws[q] & 0xFFFFu, k1 = ws[q] >> 16;
            if (k0) atomicAdd(&hist[k0 >> 4], 1);
            if (k1) atomicAdd(&hist[k1 >> 4], 1);
        }
    }
    __syncthreads();

    {
        int s = 0;
        #pragma unroll
        for (int j = 0; j < 16; j++) s += hist[base - j];
        int inc = s;
        #pragma unroll
        for (int o = 1; o < 32; o <<= 1) {
            int v = __shfl_up_sync(0xffffffffu, inc, o);
            if (lane >= o) inc += v;
        }
        if (lane == 31) warpsum[wi] = inc;
        __syncthreads();
        if (wi == 0) {
            int wsv = (lane < 8) ? warpsum[lane] : 0;
            #pragma unroll
            for (int o = 1; o < 8; o <<= 1) {
                int v = __shfl_up_sync(0xffffffffu, wsv, o);
                if (lane >= o) wsv += v;
            }
            if (lane < 8) warpsum[lane] = wsv;
        }
        __syncthreads();
        int above = inc - s + (wi ? warpsum[wi - 1] : 0);
        if (above < NCAND && above + s >= NCAND) {
            int cum = above;
            #pragma unroll
            for (int j = 0; j < 16; j++) {
                int b = base - j;
                int hb = hist[b];
                if (cum + hb >= NCAND) { sB1 = b; sAbove = cum; break; }
                cum += hb;
            }
        }
    }
    __syncthreads();
    const int B1 = sB1;

    if (B1 >= 0) {
        for (int i = tid; i < tot; i += 256) {
            uint4 u = kp4[list[i >> 4] * 16 + (i & 15)];
            uint32_t ws[4] = {u.x, u.y, u.z, u.w};
            #pragma unroll
            for (int q = 0; q < 4; q++) {
                uint32_t k0 = ws[q] & 0xFFFFu, k1 = ws[q] >> 16;
                if ((int)(k0 >> 4) == B1) atomicAdd(&sub[k0 & 15u], 1);
                if ((int)(k1 >> 4) == B1) atomicAdd(&sub[k1 & 15u], 1);
            }
        }
    }
    __syncthreads();
    if (tid == 0 && B1 >= 0) {
        int cum = sAbove;
        for (int c2 = 15; c2 >= 0; c2--) {
            cum += sub[c2];
            if (cum >= NCAND) { sThr = (B1 << 4) | c2; break; }
        }
    }
    __syncthreads();
    const uint32_t thr = (uint32_t)sThr;

    for (int i = tid; i < tot; i += 256) {
        const int j = list[i >> 4];
        const int off = i & 15;
        uint4 u = kp4[j * 16 + off];
        uint32_t ws[4] = {u.x, u.y, u.z, u.w};
        #pragma unroll
        for (int q = 0; q < 4; q++) {
            #pragma unroll
            for (int h = 0; h < 2; h++) {
                uint32_t k = h ? (ws[q] >> 16) : (ws[q] & 0xFFFFu);
                if (k >= thr) {
                    int p = atomicAdd(&sCnt, 1);
                    if (p < CAP) g_cand[row * CAP + p] = j * 128 + off * 8 + q * 2 + h;
                }
            }
        }
    }
    __syncthreads();
    if (tid == 0) g_ncand[row] = min(sCnt, CAP);
}

// ------- exact recompute (fp32 compensated, float4 loads) + top-32 ---------
__global__ __launch_bounds__(256) void k_exact(const float* __restrict__ x,
                                               const float* __restrict__ b_dec,
                                               const float* __restrict__ W,
                                               const float* __restrict__ b_enc) {
    const int row = blockIdx.x;
    __shared__ __align__(16) float sae[D_IN];
    __shared__ float vals[CAP];
    __shared__ int   cidx[CAP];
    const int tid = threadIdx.x, lane = tid & 31, wid = tid >> 5;

    {
        const float4* x4 = reinterpret_cast<const float4*>(x + (size_t)row * D_IN);
        const float4* b4 = reinterpret_cast<const float4*>(b_dec);
        float4* s4 = reinterpret_cast<float4*>(sae);
        for (int i = tid; i < D_IN / 4; i += 256) {
            float4 a = x4[i], b = b4[i];
            s4[i] = make_float4(a.x - b.x, a.y - b.y, a.z - b.z, a.w - b.w);
        }
    }
    const int nc = g_ncand[row];
    for (int i = tid; i < nc; i += 256) cidx[i] = g_cand[row * CAP + i];
    __syncthreads();

    for (int c = wid; c < nc; c += 8) {
        const int h = cidx[c];
        const float4* wr4 = reinterpret_cast<const float4*>(W + (size_t)h * D_IN);
        const float4* s4 = reinterpret_cast<const float4*>(sae);
        float s = 0.f, comp = 0.f;
        #pragma unroll 2
        for (int j = lane; j < D_IN / 4; j += 32) {
            float4 w = wr4[j], v = s4[j];
            float p[4] = {v.x * w.x, v.y * w.y, v.z * w.z, v.w * w.w};
            #pragma unroll
            for (int u = 0; u < 4; u++) {
                float t = s + p[u];
                comp += (fabsf(s) >= fabsf(p[u])) ? ((s - t) + p[u]) : ((p[u] - t) + s);
                s = t;
            }
        }
        #pragma unroll
        for (int o = 16; o; o >>= 1) {
            float s2 = __shfl_down_sync(0xffffffffu, s, o);
            float c2 = __shfl_down_sync(0xffffffffu, comp, o);
            float t = s + s2;
            float e = (fabsf(s) >= fabsf(s2)) ? ((s - t) + s2) : ((s2 - t) + s);
            s = t;
            comp = comp + c2 + e;
        }
        if (lane == 0) {
            float v = (s + comp) + b_enc[h];
            vals[c] = (v > 0.f) ? v : 0.f;
        }
    }
    __syncthreads();

    if (wid == 0) {
        for (int t = 0; t < TOPK; t++) {
            float bv = -1.f; int bi = 0x7fffffff; int bc = -1;
            for (int c = lane; c < nc; c += 32) {
                float v = vals[c]; int h = cidx[c];
                if (v > bv || (v == bv && h < bi)) { bv = v; bi = h; bc = c; }
            }
            #pragma unroll
            for (int o = 16; o; o >>= 1) {
                float ov = __shfl_down_sync(0xffffffffu, bv, o);
                int   oi = __shfl_down_sync(0xffffffffu, bi, o);
                int   oc = __shfl_down_sync(0xffffffffu, bc, o);
                if (ov > bv || (ov == bv && oi < bi)) { bv = ov; bi = oi; bc = oc; }
            }
            bv = __shfl_sync(0xffffffffu, bv, 0);
            bi = __shfl_sync(0xffffffffu, bi, 0);
            bc = __shfl_sync(0xffffffffu, bc, 0);
            if (lane == 0) {
                g_topv[row * TOPK + t] = (bc >= 0 && bv > 0.f) ? bv : 0.f;
                g_topi[row * TOPK + t] = (bc >= 0) ? bi : 0;
                if (bc >= 0) vals[bc] = -2.f;
            }
            __syncwarp();
        }
    }
}

// ---------------- decode (float4) ----------------
__global__ __launch_bounds__(256) void k_decode(const float* __restrict__ W_dec,
                                                const float* __restrict__ b_dec,
                                                float* __restrict__ out) {
    const int row = blockIdx.x;
    const int tid = threadIdx.x;
    __shared__ float v[TOPK];
    __shared__ int   hi[TOPK];
    if (tid < TOPK) {
        v[tid]  = g_topv[row * TOPK + tid];
        hi[tid] = g_topi[row * TOPK + tid];
    }
    __syncthreads();
    float4 acc = make_float4(0.f, 0.f, 0.f, 0.f);
    #pragma unroll 1
    for (int t = 0; t < TOPK; t++) {
        const float4* wr = reinterpret_cast<const float4*>(W_dec + (size_t)hi[t] * D_IN);
        const float vt = v[t];
        float4 w = wr[tid];
        acc.x += vt * w.x;
        acc.y += vt * w.y;
        acc.z += vt * w.z;
        acc.w += vt * w.w;
    }
    const float4 bd = reinterpret_cast<const float4*>(b_dec)[tid];
    acc.x += bd.x; acc.y += bd.y; acc.z += bd.z; acc.w += bd.w;
    reinterpret_cast<float4*>(out + (size_t)row * D_IN)[tid] = acc;
}

// ---------------- launcher ----------------
extern "C" void kernel_launch(void* const* d_in, const int* in_sizes, int n_in,
                              void* d_out, int out_size) {
    const float* x     = (const float*)d_in[0];
    const float* W_enc = (const float*)d_in[1];
    const float* b_enc = (const float*)d_in[2];
    const float* W_dec = (const float*)d_in[3];
    const float* b_dec = (const float*)d_in[4];
    float* out = (float*)d_out;

    cudaFuncSetAttribute(k_gemm, cudaFuncAttributeMaxDynamicSharedMemorySize, GEMM_SMEM);

    k_convW<<<2048, 256>>>(W_enc);
    k_convX<<<512, 256>>>(x, b_dec);

    dim3 g(HID / BN, B_ROWS / BM);
    k_gemm<<<g, 256, GEMM_SMEM>>>(b_enc);

    k_select<<<B_ROWS, 256>>>();
    k_exact<<<B_ROWS, 256>>>(x, b_dec, W_enc, b_enc);
    k_decode<<<B_ROWS, 256>>>(W_dec, b_dec, out);
}